// round 1
// baseline (speedup 1.0000x reference)
#include <cuda_runtime.h>

#define N_NODES 4096
#define DIN     64
#define DOUT    16
#define CCH     4
#define OUT64   64              // DOUT*CCH

// Shift-expanded B matrix: g_B[n][c*64 + r*4 + k] = support[n][r][(k-c)&3]
__device__ float g_B[(size_t)N_NODES * 256];

// ---------------------------------------------------------------------------
// Kernel A: compute support from (features, weight), expand into g_B,
// and initialize out with bias. 4 nodes per block, 256 threads.
// ---------------------------------------------------------------------------
__global__ void __launch_bounds__(256) build_B_kernel(
    const float* __restrict__ features,   // [N, DIN, C]
    const float* __restrict__ weight,     // [DIN, DOUT, C]
    const float* __restrict__ bias,       // [N, DOUT, C]
    float* __restrict__ out)              // [N, DOUT, C]
{
    __shared__ float s_w[DIN * OUT64];    // 4096 floats = 16KB
    __shared__ float s_f[4][DIN * CCH];   // 4 nodes x 256 floats
    __shared__ float s_sup[4][OUT64];

    const int tid = threadIdx.x;          // 0..255
    const int ln  = tid >> 6;             // local node 0..3
    const int o   = tid & 63;             // r*4+k
    const int n   = blockIdx.x * 4 + ln;

    // cooperative load of weight
    for (int idx = tid; idx < DIN * OUT64; idx += 256) s_w[idx] = weight[idx];
    // cooperative load of features for the 4 nodes of this block
    {
        const float* fsrc = features + (size_t)(blockIdx.x * 4) * (DIN * CCH);
        for (int idx = tid; idx < 4 * DIN * CCH; idx += 256)
            s_f[idx >> 8][idx & 255] = fsrc[idx];
    }
    __syncthreads();

    const int r = o >> 2;
    const int k = o & 3;
    float acc = 0.f;
    #pragma unroll 8
    for (int j = 0; j < DIN; j++) {
        #pragma unroll
        for (int c2 = 0; c2 < 4; c2++) {
            acc += s_f[ln][j * 4 + c2] * s_w[j * 64 + r * 4 + ((k - c2) & 3)];
        }
    }
    s_sup[ln][o] = acc;
    __syncthreads();

    // shift-expand into g_B: g_B[n][c][o] = support[n][r][(k-c)&3]
    #pragma unroll
    for (int c = 0; c < 4; c++) {
        g_B[(size_t)n * 256 + c * 64 + r * 4 + k] = s_sup[ln][r * 4 + ((k - c) & 3)];
    }
    // seed output with bias (d_out is poisoned by the harness)
    out[(size_t)n * 64 + o] = bias[(size_t)n * 64 + o];
}

// ---------------------------------------------------------------------------
// Kernel B: out[i][o] += sum_{n,c} adj[i][n][c] * g_B[n][c*64+o]
// Tall-skinny GEMM  M=4096 x K=16384 x N=64.
// Block: 256 threads = 64 outputs x 4 i-lanes, TI=64 rows, split-K by 16.
// ---------------------------------------------------------------------------
#define TI      64
#define NB      32
#define SPLIT   16
#define NCHUNK  (N_NODES / SPLIT)   // 256

__global__ void __launch_bounds__(256) gemm_kernel(
    const float* __restrict__ adj,    // [N, N, C]
    float* __restrict__ out)          // [N, DOUT, C]
{
    __shared__ float4 s_adj[TI * NB];   // [ii][nn], float4 = 4 channels -> 32KB

    const int tid   = threadIdx.x;
    const int o     = tid & 63;         // output column (r*4+k)
    const int il    = tid >> 6;         // i-lane 0..3 (each owns 16 rows)
    const int i0    = blockIdx.x * TI;
    const int nbase = blockIdx.y * NCHUNK;

    float acc[16];
    #pragma unroll
    for (int u = 0; u < 16; u++) acc[u] = 0.f;

    for (int s = 0; s < NCHUNK / NB; s++) {
        const int n0 = nbase + s * NB;

        // stage adj tile [TI x NB x 4c] into smem, float4-coalesced
        #pragma unroll
        for (int rrep = 0; rrep < (TI * NB) / 256; rrep++) {   // 8 reps
            int idx = tid + rrep * 256;
            int ii  = idx >> 5;      // /NB
            int nn  = idx & (NB - 1);
            s_adj[ii * NB + nn] =
                *(const float4*)(adj + ((size_t)(i0 + ii) * N_NODES + (n0 + nn)) * 4);
        }
        __syncthreads();

        #pragma unroll 4
        for (int nn = 0; nn < NB; nn++) {
            const float* Bn = g_B + (size_t)(n0 + nn) * 256 + o;
            const float b0 = __ldg(Bn);
            const float b1 = __ldg(Bn + 64);
            const float b2 = __ldg(Bn + 128);
            const float b3 = __ldg(Bn + 192);
            #pragma unroll
            for (int u = 0; u < 16; u++) {
                const float4 a = s_adj[(il * 16 + u) * NB + nn];  // broadcast LDS
                acc[u] += a.x * b0;
                acc[u] += a.y * b1;
                acc[u] += a.z * b2;
                acc[u] += a.w * b3;
            }
        }
        __syncthreads();
    }

    #pragma unroll
    for (int u = 0; u < 16; u++) {
        atomicAdd(&out[(size_t)(i0 + il * 16 + u) * 64 + o], acc[u]);
    }
}

// ---------------------------------------------------------------------------
// Launch
// ---------------------------------------------------------------------------
extern "C" void kernel_launch(void* const* d_in, const int* in_sizes, int n_in,
                              void* d_out, int out_size)
{
    const float* features = (const float*)d_in[0];  // [4096,64,4]
    const float* adj      = (const float*)d_in[1];  // [4096,4096,4]
    const float* weight   = (const float*)d_in[2];  // [64,16,4]
    const float* bias     = (const float*)d_in[3];  // [4096,16,4]
    float* out            = (float*)d_out;          // [4096,16,4]

    (void)in_sizes; (void)n_in; (void)out_size;

    build_B_kernel<<<N_NODES / 4, 256>>>(features, weight, bias, out);
    gemm_kernel<<<dim3(N_NODES / TI, SPLIT), 256>>>(adj, out);
}

// round 3
// speedup vs baseline: 2.7375x; 2.7375x over previous
#include <cuda_runtime.h>
#include <cstdint>

#define N_NODES 4096
#define K_TOT   16384
#define DIN     64
#define OUT64   64

#define TILE_M  128
#define KC      64
#define SPLIT   16
#define KSPAN   (K_TOT / SPLIT)   // 1024
#define NCH     (KSPAN / KC)      // 16

// Pre-split B^T (bf16 bits): g_Bh/g_Bl[o][k], 64 x 16384 row-major
__device__ unsigned short g_Bh[64 * K_TOT];
__device__ unsigned short g_Bl[64 * K_TOT];
// split-K partials: [SPLIT][4096*64]
__device__ float g_part[(size_t)SPLIT * N_NODES * OUT64];

// ---------------------------------------------------------------------------
// helpers (baseline PTX only: cp.async / ldmatrix / mma.sync — no 'a' features)
// ---------------------------------------------------------------------------
__device__ __forceinline__ uint32_t smem_u32(const void* p) {
    uint32_t a;
    asm("{ .reg .u64 t; cvta.to.shared.u64 t, %1; cvt.u32.u64 %0, t; }"
        : "=r"(a) : "l"(p));
    return a;
}

#define CP_ASYNC16(dst, src) \
    asm volatile("cp.async.cg.shared.global [%0], [%1], 16;" :: "r"(dst), "l"(src))
#define CP_COMMIT() asm volatile("cp.async.commit_group;" ::: "memory")
#define CP_WAIT0()  asm volatile("cp.async.wait_group 0;" ::: "memory")

#define LDSM_X4(r, addr) \
    asm volatile("ldmatrix.sync.aligned.m8n8.x4.shared.b16 {%0,%1,%2,%3}, [%4];" \
        : "=r"((r)[0]), "=r"((r)[1]), "=r"((r)[2]), "=r"((r)[3]) : "r"(addr))

#define MMA_BF16(d, a, b0, b1) \
    asm volatile("mma.sync.aligned.m16n8k16.row.col.f32.bf16.bf16.f32 " \
        "{%0,%1,%2,%3}, {%4,%5,%6,%7}, {%8,%9}, {%0,%1,%2,%3};" \
        : "+f"((d)[0]), "+f"((d)[1]), "+f"((d)[2]), "+f"((d)[3]) \
        : "r"((a)[0]), "r"((a)[1]), "r"((a)[2]), "r"((a)[3]), "r"(b0), "r"(b1))

#define STS64(addr, r0, r1) \
    asm volatile("st.shared.v2.b32 [%0], {%1,%2};" :: "r"(addr), "r"(r0), "r"(r1))

// smem layout (byte offsets from dynamic base, 144B padded rows):
//   Ah(buf)  @ buf*36864          (128 x 144)
//   Al(buf)  @ buf*36864 + 18432
//   Bh(buf)  @ 73728 + buf*18432  (64 x 144)
//   Bl(buf)  @ ... + 9216
#define SM_AL_OFF  18432u
#define SM_ABUF    36864u
#define SM_B0      73728u
#define SM_BL_OFF  9216u
#define SM_BBUF    18432u
#define SMEM_BYTES 110592

// ---------------------------------------------------------------------------
// Kernel A: support = circular-conv(features, weight); emit split-bf16 B^T.
// ---------------------------------------------------------------------------
__global__ void __launch_bounds__(256) build_B_kernel(
    const float* __restrict__ features,   // [N, DIN, 4]
    const float* __restrict__ weight)     // [DIN, 16, 4]
{
    __shared__ float s_w[DIN * OUT64];
    __shared__ float s_f[4][DIN * 4];
    __shared__ float s_sup[4][OUT64];

    const int tid = threadIdx.x;
    const int ln  = tid >> 6;
    const int o   = tid & 63;
    const int n   = blockIdx.x * 4 + ln;

    for (int idx = tid; idx < DIN * OUT64; idx += 256) s_w[idx] = weight[idx];
    {
        const float* fsrc = features + (size_t)(blockIdx.x * 4) * (DIN * 4);
        for (int idx = tid; idx < 4 * DIN * 4; idx += 256)
            s_f[idx >> 8][idx & 255] = fsrc[idx];
    }
    __syncthreads();

    const int r = o >> 2;
    const int k = o & 3;
    float acc = 0.f;
    #pragma unroll 8
    for (int j = 0; j < DIN; j++) {
        #pragma unroll
        for (int c = 0; c < 4; c++)
            acc += s_f[ln][j * 4 + c] * s_w[j * 64 + r * 4 + ((k - c) & 3)];
    }
    s_sup[ln][o] = acc;
    __syncthreads();

    // Bt[o][n*4+c] = support[n][o>>2][((o&3)-c)&3], split into hi/lo bf16
    uint32_t h01 = 0, h23 = 0, l01 = 0, l23 = 0;
    #pragma unroll
    for (int c = 0; c < 4; c++) {
        float v = s_sup[ln][r * 4 + ((k - c) & 3)];
        uint32_t b  = __float_as_uint(v);
        uint32_t hb = b & 0xFFFF0000u;
        float lof   = v - __uint_as_float(hb);
        uint32_t hs = b >> 16, ls = __float_as_uint(lof) >> 16;
        if (c < 2) { h01 |= hs << (16 * c); l01 |= ls << (16 * c); }
        else       { h23 |= hs << (16 * (c - 2)); l23 |= ls << (16 * (c - 2)); }
    }
    size_t off = (size_t)o * K_TOT + (size_t)n * 4;
    *(uint2*)(&g_Bh[off]) = make_uint2(h01, h23);
    *(uint2*)(&g_Bl[off]) = make_uint2(l01, l23);
}

// ---------------------------------------------------------------------------
// GEMM pieces
// ---------------------------------------------------------------------------
__device__ __forceinline__ void loadB(uint32_t dstbase, int kk0, int tid)
{
    #pragma unroll
    for (int i = 0; i < 2; i++) {
        int e = tid + i * 256;
        int row = e >> 3, jj = e & 7;          // 64 rows x 8 16B-chunks
        uint32_t d = dstbase + (uint32_t)row * 144u + (uint32_t)jj * 16u;
        const char* sh = (const char*)g_Bh + ((size_t)row * K_TOT + kk0) * 2 + jj * 16;
        const char* sl = (const char*)g_Bl + ((size_t)row * K_TOT + kk0) * 2 + jj * 16;
        CP_ASYNC16(d, sh);
        CP_ASYNC16(d + SM_BL_OFF, sl);
    }
}

__device__ __forceinline__ void storeA(uint32_t abase, const uint4* v,
                                       int arow, int aj)
{
    #pragma unroll
    for (int i = 0; i < 8; i++) {
        uint32_t x = v[i].x, y = v[i].y, z = v[i].z, w = v[i].w;
        uint32_t h0 = __byte_perm(x, y, 0x7632);
        uint32_t h1 = __byte_perm(z, w, 0x7632);
        float lx = __uint_as_float(x) - __uint_as_float(x & 0xFFFF0000u);
        float ly = __uint_as_float(y) - __uint_as_float(y & 0xFFFF0000u);
        float lz = __uint_as_float(z) - __uint_as_float(z & 0xFFFF0000u);
        float lw = __uint_as_float(w) - __uint_as_float(w & 0xFFFF0000u);
        uint32_t l0 = __byte_perm(__float_as_uint(lx), __float_as_uint(ly), 0x7632);
        uint32_t l1 = __byte_perm(__float_as_uint(lz), __float_as_uint(lw), 0x7632);
        uint32_t ad = abase + (uint32_t)(arow + i * 16) * 144u + (uint32_t)aj * 8u;
        STS64(ad, h0, h1);
        STS64(ad + SM_AL_OFF, l0, l1);
    }
}

// out_partial[i][o] = sum_k adj[i][k] * Bt[o][k] over this block's K-range.
// D = Ah*Bh + Al*Bh + Ah*Bl via mma.sync m16n8k16 bf16.
__global__ void __launch_bounds__(256, 2) gemm_mma(const float* __restrict__ adj)
{
    extern __shared__ __align__(16) char sm[];
    const uint32_t base = smem_u32(sm);
    const int tid  = threadIdx.x;
    const int wid  = tid >> 5;
    const int lane = tid & 31;
    const int i0    = blockIdx.x * TILE_M;
    const int kbase = blockIdx.y * KSPAN;

    const int arow = tid >> 4;   // 0..15 (A staging row base)
    const int aj   = tid & 15;   // float4 column

    float acc[8][4];
    #pragma unroll
    for (int j = 0; j < 8; j++)
        #pragma unroll
        for (int q = 0; q < 4; q++) acc[j][q] = 0.f;

    uint4 v[8];
    // prologue: chunk 0
    #pragma unroll
    for (int i = 0; i < 8; i++)
        v[i] = *(const uint4*)(adj + (size_t)(i0 + arow + i * 16) * K_TOT + kbase + aj * 4);
    loadB(base + SM_B0, kbase, tid);
    CP_COMMIT();
    storeA(base, v, arow, aj);

    const uint32_t lrow = (uint32_t)(lane & 15);
    const uint32_t lk   = (uint32_t)(lane & 16);

    for (int s = 0; s < NCH; s++) {
        const int b = s & 1;
        if (s + 1 < NCH) {
            const int kk = kbase + (s + 1) * KC;
            #pragma unroll
            for (int i = 0; i < 8; i++)
                v[i] = *(const uint4*)(adj + (size_t)(i0 + arow + i * 16) * K_TOT + kk + aj * 4);
        }
        CP_WAIT0();
        __syncthreads();
        if (s + 1 < NCH) {
            loadB(base + SM_B0 + (uint32_t)(b ^ 1) * SM_BBUF, kbase + (s + 1) * KC, tid);
            CP_COMMIT();
            storeA(base + (uint32_t)(b ^ 1) * SM_ABUF, v, arow, aj);
        }

        const uint32_t sA = base + (uint32_t)b * SM_ABUF;
        const uint32_t sB = base + SM_B0 + (uint32_t)b * SM_BBUF;
        #pragma unroll
        for (int ks = 0; ks < 4; ks++) {
            uint32_t aaddr = sA + (uint32_t)(wid * 16) * 144u + lrow * 144u
                           + (uint32_t)(ks * 32) + lk;
            uint32_t ah[4], al[4];
            LDSM_X4(ah, aaddr);
            LDSM_X4(al, aaddr + SM_AL_OFF);
            #pragma unroll
            for (int jp = 0; jp < 4; jp++) {
                uint32_t baddr = sB + (uint32_t)(jp * 16) * 144u + lrow * 144u
                               + (uint32_t)(ks * 32) + lk;
                uint32_t bh[4], bl[4];
                LDSM_X4(bh, baddr);
                LDSM_X4(bl, baddr + SM_BL_OFF);
                MMA_BF16(acc[2 * jp],     ah, bh[0], bh[2]);
                MMA_BF16(acc[2 * jp],     al, bh[0], bh[2]);
                MMA_BF16(acc[2 * jp],     ah, bl[0], bl[2]);
                MMA_BF16(acc[2 * jp + 1], ah, bh[1], bh[3]);
                MMA_BF16(acc[2 * jp + 1], al, bh[1], bh[3]);
                MMA_BF16(acc[2 * jp + 1], ah, bl[1], bl[3]);
            }
        }
    }

    // write split-K partial (coalesced-ish float2 stores)
    float* p = g_part + (size_t)blockIdx.y * (N_NODES * OUT64);
    const int r0 = i0 + wid * 16 + (lane >> 2);
    const int c0 = (lane & 3) * 2;
    #pragma unroll
    for (int j = 0; j < 8; j++) {
        *(float2*)&p[(size_t)r0 * 64 + j * 8 + c0]       = make_float2(acc[j][0], acc[j][1]);
        *(float2*)&p[(size_t)(r0 + 8) * 64 + j * 8 + c0] = make_float2(acc[j][2], acc[j][3]);
    }
}

// ---------------------------------------------------------------------------
// Reduce: out = bias + sum over SPLIT partials
// ---------------------------------------------------------------------------
__global__ void __launch_bounds__(256) reduce_k(
    const float* __restrict__ bias, float* __restrict__ out)
{
    const int idx = blockIdx.x * 256 + threadIdx.x;   // float4 index, 65536 total
    float4 s = ((const float4*)bias)[idx];
    #pragma unroll
    for (int t = 0; t < SPLIT; t++) {
        float4 q = *(const float4*)&g_part[(size_t)t * (N_NODES * OUT64) + (size_t)idx * 4];
        s.x += q.x; s.y += q.y; s.z += q.z; s.w += q.w;
    }
    ((float4*)out)[idx] = s;
}

// ---------------------------------------------------------------------------
extern "C" void kernel_launch(void* const* d_in, const int* in_sizes, int n_in,
                              void* d_out, int out_size)
{
    const float* features = (const float*)d_in[0];
    const float* adj      = (const float*)d_in[1];
    const float* weight   = (const float*)d_in[2];
    const float* bias     = (const float*)d_in[3];
    float* out            = (float*)d_out;
    (void)in_sizes; (void)n_in; (void)out_size;

    cudaFuncSetAttribute(gemm_mma, cudaFuncAttributeMaxDynamicSharedMemorySize, SMEM_BYTES);

    build_B_kernel<<<N_NODES / 4, 256>>>(features, weight);
    gemm_mma<<<dim3(N_NODES / TILE_M, SPLIT), 256, SMEM_BYTES>>>(adj);
    reduce_k<<<(N_NODES * OUT64 / 4) / 256, 256>>>(bias, out);
}

// round 4
// speedup vs baseline: 2.9092x; 1.0627x over previous
#include <cuda_runtime.h>
#include <cstdint>

#define N_NODES 4096
#define K_TOT   16384
#define DIN     64
#define OUT64   64

#define TILE_M  128
#define KC      64
#define SPLIT   16
#define KSPAN   (K_TOT / SPLIT)   // 1024
#define NCH     (KSPAN / KC)      // 16

// Pre-split B^T (bf16 bits): g_Bh/g_Bl[o][k], 64 x 16384 row-major
__device__ unsigned short g_Bh[64 * K_TOT];
__device__ unsigned short g_Bl[64 * K_TOT];
// split-K partials: [SPLIT][4096*64]
__device__ float g_part[(size_t)SPLIT * N_NODES * OUT64];

// ---------------------------------------------------------------------------
// helpers (baseline PTX only: cp.async / ldmatrix / mma.sync)
// ---------------------------------------------------------------------------
__device__ __forceinline__ uint32_t smem_u32(const void* p) {
    uint32_t a;
    asm("{ .reg .u64 t; cvta.to.shared.u64 t, %1; cvt.u32.u64 %0, t; }"
        : "=r"(a) : "l"(p));
    return a;
}

#define CP_ASYNC16(dst, src) \
    asm volatile("cp.async.cg.shared.global [%0], [%1], 16;" :: "r"(dst), "l"(src))
#define CP_COMMIT() asm volatile("cp.async.commit_group;" ::: "memory")
#define CP_WAIT0()  asm volatile("cp.async.wait_group 0;" ::: "memory")

#define LDSM_X4(r, addr) \
    asm volatile("ldmatrix.sync.aligned.m8n8.x4.shared.b16 {%0,%1,%2,%3}, [%4];" \
        : "=r"((r)[0]), "=r"((r)[1]), "=r"((r)[2]), "=r"((r)[3]) : "r"(addr))

#define MMA_BF16(d, a, b0, b1) \
    asm volatile("mma.sync.aligned.m16n8k16.row.col.f32.bf16.bf16.f32 " \
        "{%0,%1,%2,%3}, {%4,%5,%6,%7}, {%8,%9}, {%0,%1,%2,%3};" \
        : "+f"((d)[0]), "+f"((d)[1]), "+f"((d)[2]), "+f"((d)[3]) \
        : "r"((a)[0]), "r"((a)[1]), "r"((a)[2]), "r"((a)[3]), "r"(b0), "r"(b1))

// smem: B only, double-buffered. 64 rows x 144B per (hi|lo) plane.
#define SM_BL_OFF  9216u
#define SM_BBUF    18432u
#define SMEM_BYTES 36864

// ---------------------------------------------------------------------------
// Kernel A: support = circular-conv(features, weight); emit split-bf16 B^T.
// 256 blocks x 256 threads, 16 nodes per block (weight loaded once).
// ---------------------------------------------------------------------------
__global__ void __launch_bounds__(256) build_B_kernel(
    const float* __restrict__ features,   // [N, DIN, 4]
    const float* __restrict__ weight)     // [DIN, 16, 4]
{
    __shared__ float s_w[DIN * OUT64];     // 16KB
    __shared__ float s_f[4 * DIN * 4];     // 4 nodes x 256 floats

    const int tid  = threadIdx.x;
    const int lane = tid & 31;
    const int ln   = tid >> 6;             // local node 0..3
    const int o    = tid & 63;             // r*4+k
    const int r    = o >> 2;
    const int k    = o & 3;

    #pragma unroll
    for (int i = 0; i < 4; i++)
        ((float4*)s_w)[tid + i * 256] = ((const float4*)weight)[tid + i * 256];

    for (int ng = 0; ng < 4; ng++) {
        __syncthreads();   // s_w ready (ng=0) / s_f reuse safe (ng>0)
        const int nb = blockIdx.x * 16 + ng * 4;
        ((float4*)s_f)[tid] = ((const float4*)(features + (size_t)nb * 256))[tid];
        __syncthreads();

        float acc = 0.f;
        const float* fp = s_f + ln * 256;
        #pragma unroll 8
        for (int j = 0; j < DIN; j++) {
            #pragma unroll
            for (int c = 0; c < 4; c++)
                acc += fp[j * 4 + c] * s_w[j * 64 + r * 4 + ((k - c) & 3)];
        }

        // gather the 4 channel-shifts via intra-quad shuffle
        uint32_t h01 = 0, h23 = 0, l01 = 0, l23 = 0;
        #pragma unroll
        for (int c = 0; c < 4; c++) {
            float v = __shfl_sync(0xffffffffu, acc, (lane & ~3) | ((k - c) & 3));
            uint32_t b  = __float_as_uint(v);
            float lof   = v - __uint_as_float(b & 0xFFFF0000u);
            uint32_t hs = b >> 16, ls = __float_as_uint(lof) >> 16;
            if (c < 2) { h01 |= hs << (16 * c); l01 |= ls << (16 * c); }
            else       { h23 |= hs << (16 * (c - 2)); l23 |= ls << (16 * (c - 2)); }
        }
        const int n = nb + ln;
        size_t off = (size_t)o * K_TOT + (size_t)n * 4;
        *(uint2*)(&g_Bh[off]) = make_uint2(h01, h23);
        *(uint2*)(&g_Bl[off]) = make_uint2(l01, l23);
    }
}

// ---------------------------------------------------------------------------
// B tile loader: hi/lo bf16 [64 o-rows x 64 k], 144B-padded rows
// ---------------------------------------------------------------------------
__device__ __forceinline__ void loadB(uint32_t dstbase, int kk0, int tid)
{
    #pragma unroll
    for (int i = 0; i < 2; i++) {
        int e = tid + i * 256;
        int row = e >> 3, jj = e & 7;
        uint32_t d = dstbase + (uint32_t)row * 144u + (uint32_t)jj * 16u;
        const char* sh = (const char*)g_Bh + ((size_t)row * K_TOT + kk0) * 2 + jj * 16;
        const char* sl = (const char*)g_Bl + ((size_t)row * K_TOT + kk0) * 2 + jj * 16;
        CP_ASYNC16(d, sh);
        CP_ASYNC16(d + SM_BL_OFF, sl);
    }
}

__device__ __forceinline__ void cvt2(float x, float y, uint32_t& h, uint32_t& l)
{
    uint32_t bx = __float_as_uint(x), by = __float_as_uint(y);
    h = __byte_perm(bx, by, 0x7632);
    float lx = x - __uint_as_float(bx & 0xFFFF0000u);
    float ly = y - __uint_as_float(by & 0xFFFF0000u);
    l = __byte_perm(__float_as_uint(lx), __float_as_uint(ly), 0x7632);
}

// ---------------------------------------------------------------------------
// GEMM: partial[i][o] = sum_k adj[i][k] * Bt[o][k] over this block's K-range.
// D = Ah*Bh + Al*Bh + Ah*Bl. A fragments loaded directly from global memory.
// Warp tile: 32 rows x 32 cols. grid (32, 16), 256 threads.
// ---------------------------------------------------------------------------
__global__ void __launch_bounds__(256, 2) gemm_mma(const float* __restrict__ adj)
{
    extern __shared__ __align__(16) char sm[];
    const uint32_t base = smem_u32(sm);
    const int tid  = threadIdx.x;
    const int wid  = tid >> 5;
    const int lane = tid & 31;
    const int g    = lane >> 2;          // fragment row within 8
    const int t    = lane & 3;           // fragment col pair
    const int i0    = blockIdx.x * TILE_M;
    const int kbase = blockIdx.y * KSPAN;

    const int rowgrp  = (wid & 3) * 32;        // warp's 32-row group
    const int colhalf = (wid >> 2) * 32;       // warp's 32-col half

    float acc[2][4][4];
    #pragma unroll
    for (int m = 0; m < 2; m++)
        #pragma unroll
        for (int j = 0; j < 4; j++)
            #pragma unroll
            for (int q = 0; q < 4; q++) acc[m][j][q] = 0.f;

    // per-thread A row base pointers (row g of each 16-row m-tile)
    const float* ap0 = adj + (size_t)(i0 + rowgrp + g) * K_TOT + kbase + 2 * t;
    const float* ap1 = ap0 + (size_t)16 * K_TOT;

    loadB(base, kbase, tid);
    CP_COMMIT();

    const uint32_t lrow = (uint32_t)(lane & 15);
    const uint32_t lkb  = (uint32_t)(lane & 16);

    for (int s = 0; s < NCH; s++) {
        const int b = s & 1;
        CP_WAIT0();
        __syncthreads();
        if (s + 1 < NCH) {
            loadB(base + (uint32_t)(b ^ 1) * SM_BBUF, kbase + (s + 1) * KC, tid);
            CP_COMMIT();
        }

        const uint32_t sB = base + (uint32_t)b * SM_BBUF;
        const int koff = s * KC;

        #pragma unroll
        for (int ks = 0; ks < 4; ks++) {
            // A fragments for both 16-row m-tiles, direct from global
            uint32_t ah[2][4], al[2][4];
            #pragma unroll
            for (int m = 0; m < 2; m++) {
                const float* rp = (m == 0) ? ap0 : ap1;
                const float* q0 = rp + koff + ks * 16;
                float2 p0 = *(const float2*)(q0);                      // row g,   k-lo
                float2 p1 = *(const float2*)(q0 + 8 * K_TOT);          // row g+8, k-lo
                float2 p2 = *(const float2*)(q0 + 8);                  // row g,   k-hi
                float2 p3 = *(const float2*)(q0 + 8 * K_TOT + 8);      // row g+8, k-hi
                cvt2(p0.x, p0.y, ah[m][0], al[m][0]);
                cvt2(p1.x, p1.y, ah[m][1], al[m][1]);
                cvt2(p2.x, p2.y, ah[m][2], al[m][2]);
                cvt2(p3.x, p3.y, ah[m][3], al[m][3]);
            }
            #pragma unroll
            for (int jp = 0; jp < 2; jp++) {
                uint32_t baddr = sB + (uint32_t)(colhalf + jp * 16 + lrow) * 144u
                               + (uint32_t)(ks * 32) + lkb;
                uint32_t bh[4], bl[4];
                LDSM_X4(bh, baddr);
                LDSM_X4(bl, baddr + SM_BL_OFF);
                #pragma unroll
                for (int m = 0; m < 2; m++) {
                    MMA_BF16(acc[m][jp * 2],     ah[m], bh[0], bh[2]);
                    MMA_BF16(acc[m][jp * 2],     al[m], bh[0], bh[2]);
                    MMA_BF16(acc[m][jp * 2],     ah[m], bl[0], bl[2]);
                    MMA_BF16(acc[m][jp * 2 + 1], ah[m], bh[1], bh[3]);
                    MMA_BF16(acc[m][jp * 2 + 1], al[m], bh[1], bh[3]);
                    MMA_BF16(acc[m][jp * 2 + 1], ah[m], bl[1], bl[3]);
                }
            }
        }
    }

    // write split-K partials
    float* p = g_part + (size_t)blockIdx.y * (N_NODES * OUT64);
    #pragma unroll
    for (int m = 0; m < 2; m++) {
        const int r0 = i0 + rowgrp + m * 16 + g;
        #pragma unroll
        for (int j = 0; j < 4; j++) {
            const int c0 = colhalf + j * 8 + 2 * t;
            *(float2*)&p[(size_t)r0 * 64 + c0]       = make_float2(acc[m][j][0], acc[m][j][1]);
            *(float2*)&p[(size_t)(r0 + 8) * 64 + c0] = make_float2(acc[m][j][2], acc[m][j][3]);
        }
    }
}

// ---------------------------------------------------------------------------
// Reduce: out = bias + sum over SPLIT partials
// ---------------------------------------------------------------------------
__global__ void __launch_bounds__(256) reduce_k(
    const float* __restrict__ bias, float* __restrict__ out)
{
    const int idx = blockIdx.x * 256 + threadIdx.x;   // float4 index
    float4 s = ((const float4*)bias)[idx];
    #pragma unroll
    for (int tt = 0; tt < SPLIT; tt++) {
        float4 q = *(const float4*)&g_part[(size_t)tt * (N_NODES * OUT64) + (size_t)idx * 4];
        s.x += q.x; s.y += q.y; s.z += q.z; s.w += q.w;
    }
    ((float4*)out)[idx] = s;
}

// ---------------------------------------------------------------------------
extern "C" void kernel_launch(void* const* d_in, const int* in_sizes, int n_in,
                              void* d_out, int out_size)
{
    const float* features = (const float*)d_in[0];
    const float* adj      = (const float*)d_in[1];
    const float* weight   = (const float*)d_in[2];
    const float* bias     = (const float*)d_in[3];
    float* out            = (float*)d_out;
    (void)in_sizes; (void)n_in; (void)out_size;

    cudaFuncSetAttribute(gemm_mma, cudaFuncAttributeMaxDynamicSharedMemorySize, SMEM_BYTES);

    build_B_kernel<<<256, 256>>>(features, weight);
    gemm_mma<<<dim3(N_NODES / TILE_M, SPLIT), 256, SMEM_BYTES>>>(adj);
    reduce_k<<<(N_NODES * OUT64 / 4) / 256, 256>>>(bias, out);
}